// round 12
// baseline (speedup 1.0000x reference)
#include <cuda_runtime.h>
#include <cuda_fp16.h>
#include <cstdint>

#define N_NODES 65536
#define N_EDGES 1048576
#define FEAT    64

// ------------------------- device scratch (no allocs) -----------------------
__device__ __align__(16) __half g_support_h[(size_t)N_NODES * FEAT]; // 8 MB
__device__ __align__(16) int   g_cnt[N_NODES];   // zero-init; self-cleaned per run
__device__ __align__(16) int   g_rs[N_NODES + 4];
__device__ __align__(16) int   g_cur[N_NODES];
__device__ __align__(16) int   g_bsum[64];
__device__ __align__(16) int2  g_epair[N_EDGES];
__device__ unsigned g_barcnt;
__device__ unsigned g_bargen;

// ---- packed f32x2 helpers ---------------------------------------------------
__device__ __forceinline__ unsigned long long pk2(float x, float y) {
    unsigned long long r;
    asm("mov.b64 %0, {%1, %2};" : "=l"(r) : "f"(x), "f"(y));
    return r;
}
__device__ __forceinline__ void fma2(unsigned long long& d,
                                     unsigned long long a, unsigned long long b) {
    asm("fma.rn.f32x2 %0, %1, %2, %0;" : "+l"(d) : "l"(a), "l"(b));
}
__device__ __forceinline__ float2 up2(unsigned long long v) {
    float2 f;
    asm("mov.b64 {%0, %1}, %2;" : "=f"(f.x), "=f"(f.y) : "l"(v));
    return f;
}

// ---------------------------------------------------------------------------
// Kernel A (main stream): pure GEMM  support = X @ W  (fp16 out)
// ---------------------------------------------------------------------------
__global__ __launch_bounds__(256) void gemm64(const float* __restrict__ X,
                                              const float* __restrict__ W) {
    __shared__ float4 Ws[64][16];
    __shared__ float4 Xs[64][16];

    const int tid  = threadIdx.x;
    const int base = blockIdx.x * 64;

    const float4* X4 = (const float4*)(X + (size_t)base * FEAT);
    const float4* W4 = (const float4*)W;
    float4* XsF = (float4*)Xs;
    float4* WsF = (float4*)Ws;
#pragma unroll
    for (int i = 0; i < 4; i++) {
        const int idx = tid + i * 256;
        XsF[idx] = X4[idx];
        WsF[idx] = W4[idx];
    }
    __syncthreads();

    const int rt = tid >> 4;
    const int ct = tid & 15;

    unsigned long long acc[4][2];
#pragma unroll
    for (int i = 0; i < 4; i++) { acc[i][0] = pk2(0.f, 0.f); acc[i][1] = pk2(0.f, 0.f); }

#pragma unroll
    for (int kk = 0; kk < 16; kk++) {
        const float4 w0 = Ws[kk * 4 + 0][ct];
        const float4 w1 = Ws[kk * 4 + 1][ct];
        const float4 w2 = Ws[kk * 4 + 2][ct];
        const float4 w3 = Ws[kk * 4 + 3][ct];
        const unsigned long long wp00 = pk2(w0.x, w0.y), wp01 = pk2(w0.z, w0.w);
        const unsigned long long wp10 = pk2(w1.x, w1.y), wp11 = pk2(w1.z, w1.w);
        const unsigned long long wp20 = pk2(w2.x, w2.y), wp21 = pk2(w2.z, w2.w);
        const unsigned long long wp30 = pk2(w3.x, w3.y), wp31 = pk2(w3.z, w3.w);
#pragma unroll
        for (int i = 0; i < 4; i++) {
            const float4 x = Xs[rt + 16 * i][kk];
            unsigned long long xx;
            xx = pk2(x.x, x.x); fma2(acc[i][0], xx, wp00); fma2(acc[i][1], xx, wp01);
            xx = pk2(x.y, x.y); fma2(acc[i][0], xx, wp10); fma2(acc[i][1], xx, wp11);
            xx = pk2(x.z, x.z); fma2(acc[i][0], xx, wp20); fma2(acc[i][1], xx, wp21);
            xx = pk2(x.w, x.w); fma2(acc[i][0], xx, wp30); fma2(acc[i][1], xx, wp31);
        }
    }

#pragma unroll
    for (int i = 0; i < 4; i++) {
        const int row = base + rt + 16 * i;
        const float2 a = up2(acc[i][0]);
        const float2 b = up2(acc[i][1]);
        const __half2 ha = __floats2half2_rn(a.x, a.y);
        const __half2 hb = __floats2half2_rn(b.x, b.y);
        uint2 st;
        st.x = *(const unsigned*)&ha;
        st.y = *(const unsigned*)&hb;
        *(uint2*)(g_support_h + (size_t)row * FEAT + ct * 4) = st;
    }
}

// ---------------------------------------------------------------------------
// Kernel B1 (side stream): histogram of destination rows
// ---------------------------------------------------------------------------
__global__ __launch_bounds__(256) void hist(const int4* __restrict__ erow4) {
    const unsigned i = blockIdx.x * 256u + threadIdx.x;
    const int4 r = erow4[i];
    atomicAdd(&g_cnt[r.x], 1);
    atomicAdd(&g_cnt[r.y], 1);
    atomicAdd(&g_cnt[r.z], 1);
    atomicAdd(&g_cnt[r.w], 1);
}

// ---------------------------------------------------------------------------
// Kernel B2: full CSR scan (64 blocks, internal grid barrier). Self-cleans cnt.
// ---------------------------------------------------------------------------
__device__ __forceinline__ void gbar64() {
    __syncthreads();
    if (threadIdx.x == 0) {
        __threadfence();
        const unsigned gen = *(volatile unsigned*)&g_bargen;
        if (atomicAdd(&g_barcnt, 1u) == 63u) {
            g_barcnt = 0;
            __threadfence();
            *(volatile unsigned*)&g_bargen = gen + 1u;
        } else {
            while (*(volatile unsigned*)&g_bargen == gen) { __nanosleep(32); }
        }
    }
    __syncthreads();
}

__global__ __launch_bounds__(256) void scan_fused() {
    __shared__ int wsum[8];
    const int tid = threadIdx.x;
    const int bid = blockIdx.x;
    const int i = bid * 256 + tid;

    const int4 c = ((const int4*)g_cnt)[i];
    const int s = c.x + c.y + c.z + c.w;

    const int lane = tid & 31, wid = tid >> 5;
    int x = s;
#pragma unroll
    for (int d = 1; d < 32; d <<= 1) {
        const int y = __shfl_up_sync(0xFFFFFFFFu, x, d);
        if (lane >= d) x += y;
    }
    if (lane == 31) wsum[wid] = x;
    __syncthreads();
    if (wid == 0) {
        int w = (lane < 8) ? wsum[lane] : 0;
#pragma unroll
        for (int d = 1; d < 8; d <<= 1) {
            const int y = __shfl_up_sync(0xFFFFFFFFu, w, d);
            if (lane >= d) w += y;
        }
        if (lane < 8) wsum[lane] = w;
    }
    __syncthreads();
    const int incl = x + (wid > 0 ? wsum[wid - 1] : 0);
    const int ex = incl - s;
    if (tid == 255) g_bsum[bid] = incl;
    gbar64();

    if (bid == 0 && tid < 32) {
        const int a = __ldcg(&g_bsum[tid]);
        const int b = __ldcg(&g_bsum[tid + 32]);
        int ia = a, ib = b;
#pragma unroll
        for (int d = 1; d < 32; d <<= 1) {
            const int ya = __shfl_up_sync(0xFFFFFFFFu, ia, d);
            const int yb = __shfl_up_sync(0xFFFFFFFFu, ib, d);
            if (tid >= d) { ia += ya; ib += yb; }
        }
        const int lowtot = __shfl_sync(0xFFFFFFFFu, ia, 31);
        g_bsum[tid]      = ia - a;
        g_bsum[tid + 32] = lowtot + ib - b;
    }
    gbar64();

    const int off = __ldcg(&g_bsum[bid]) + ex;
    const int4 rs = make_int4(off, off + c.x, off + c.x + c.y, off + c.x + c.y + c.z);
    ((int4*)g_rs)[i]  = rs;
    ((int4*)g_cur)[i] = rs;
    ((int4*)g_cnt)[i] = make_int4(0, 0, 0, 0);
    if (i == 0) g_rs[N_NODES] = N_EDGES;
}

// ---------------------------------------------------------------------------
// Kernel B3: reorder edges into CSR (col, val) pairs
// ---------------------------------------------------------------------------
__global__ __launch_bounds__(256) void reorder(const int4*   __restrict__ erow4,
                                               const int4*   __restrict__ ecol4,
                                               const float4* __restrict__ eval4) {
    const unsigned i = blockIdx.x * 256u + threadIdx.x;
    const int4   r = erow4[i];
    const int4   c = ecol4[i];
    const float4 v = eval4[i];
    int p;
    p = atomicAdd(&g_cur[r.x], 1); g_epair[p] = make_int2(c.x, __float_as_int(v.x));
    p = atomicAdd(&g_cur[r.y], 1); g_epair[p] = make_int2(c.y, __float_as_int(v.y));
    p = atomicAdd(&g_cur[r.z], 1); g_epair[p] = make_int2(c.z, __float_as_int(v.z));
    p = atomicAdd(&g_cur[r.w], 1); g_epair[p] = make_int2(c.w, __float_as_int(v.w));
}

// ---------------------------------------------------------------------------
// Kernel C: SpMM + bias + ReLU. One row per warp; lane = (edge-slot g, feat-octet fo).
// 4 edges per step (unroll 2 -> 8), uint4 gathers, predicated tail, shfl reduce.
// ---------------------------------------------------------------------------
__global__ __launch_bounds__(256) void spmm4(float* __restrict__ out,
                                             const float* __restrict__ bias) {
    const int lane = threadIdx.x & 31;
    const int g    = lane >> 3;          // edge slot 0..3
    const int fo   = lane & 7;           // feature octet 0..7
    const int r    = blockIdx.x * 8 + (threadIdx.x >> 5);

    const int s = g_rs[r];
    const int e = g_rs[r + 1];
    const __half* supp = g_support_h;

    float acc[8];
#pragma unroll
    for (int j = 0; j < 8; j++) acc[j] = 0.f;

    for (int i = s; i < e; i += 8) {
        const int i0 = i + g;
        const int i1 = i + 4 + g;
        const int2 p0 = g_epair[i0 < e ? i0 : s];
        const int2 p1 = g_epair[i1 < e ? i1 : s];
        const float v0 = (i0 < e) ? __int_as_float(p0.y) : 0.f;
        const float v1 = (i1 < e) ? __int_as_float(p1.y) : 0.f;
        const uint4 h0 = *(const uint4*)(supp + ((size_t)p0.x << 6) + (fo << 3));
        const uint4 h1 = *(const uint4*)(supp + ((size_t)p1.x << 6) + (fo << 3));
        float2 f;
        f = __half22float2(*(const __half2*)&h0.x); acc[0] += v0 * f.x; acc[1] += v0 * f.y;
        f = __half22float2(*(const __half2*)&h0.y); acc[2] += v0 * f.x; acc[3] += v0 * f.y;
        f = __half22float2(*(const __half2*)&h0.z); acc[4] += v0 * f.x; acc[5] += v0 * f.y;
        f = __half22float2(*(const __half2*)&h0.w); acc[6] += v0 * f.x; acc[7] += v0 * f.y;
        f = __half22float2(*(const __half2*)&h1.x); acc[0] += v1 * f.x; acc[1] += v1 * f.y;
        f = __half22float2(*(const __half2*)&h1.y); acc[2] += v1 * f.x; acc[3] += v1 * f.y;
        f = __half22float2(*(const __half2*)&h1.z); acc[4] += v1 * f.x; acc[5] += v1 * f.y;
        f = __half22float2(*(const __half2*)&h1.w); acc[6] += v1 * f.x; acc[7] += v1 * f.y;
    }

    // reduce across the 4 edge slots (lanes fo, fo+8, fo+16, fo+24)
#pragma unroll
    for (int d = 8; d <= 16; d <<= 1) {
#pragma unroll
        for (int j = 0; j < 8; j++)
            acc[j] += __shfl_xor_sync(0xFFFFFFFFu, acc[j], d);
    }

    // lanes 0..7 (g==0) write features [fo*8, fo*8+4); lanes 8..15 (g==1) the rest
    if (lane < 16) {
        const int half = g;              // 0 or 1
        const float4 b = *(const float4*)(bias + fo * 8 + half * 4);
        float4 o;
        o.x = fmaxf(acc[half * 4 + 0] + b.x, 0.f);
        o.y = fmaxf(acc[half * 4 + 1] + b.y, 0.f);
        o.z = fmaxf(acc[half * 4 + 2] + b.z, 0.f);
        o.w = fmaxf(acc[half * 4 + 3] + b.w, 0.f);
        *(float4*)(out + ((size_t)r << 6) + fo * 8 + half * 4) = o;
    }
}

// ---------------------------------------------------------------------------
extern "C" void kernel_launch(void* const* d_in, const int* in_sizes, int n_in,
                              void* d_out, int out_size) {
    const float* X    = (const float*)d_in[0];
    const int*   erow = (const int*)  d_in[1];
    const int*   ecol = (const int*)  d_in[2];
    const float* eval = (const float*)d_in[3];
    const float* W    = (const float*)d_in[4];
    const float* bias = (const float*)d_in[5];
    float* out = (float*)d_out;

    // Fork a side stream for the CSR chain; GEMM (fma-bound) overlaps it
    // (latency/LTS-bound). Host-side resources only; intentionally not
    // destroyed (kernel_launch is called only a handful of times, and the
    // captured graph references the side-stream nodes).
    cudaStream_t s2;
    cudaStreamCreateWithFlags(&s2, cudaStreamNonBlocking);
    cudaEvent_t eFork, eJoin;
    cudaEventCreateWithFlags(&eFork, cudaEventDisableTiming);
    cudaEventCreateWithFlags(&eJoin, cudaEventDisableTiming);

    cudaEventRecord(eFork, 0);
    cudaStreamWaitEvent(s2, eFork, 0);

    gemm64<<<N_NODES / 64, 256>>>(X, W);                       // main stream

    hist<<<N_EDGES / 1024, 256, 0, s2>>>((const int4*)erow);   // side stream
    scan_fused<<<64, 256, 0, s2>>>();
    reorder<<<N_EDGES / 1024, 256, 0, s2>>>((const int4*)erow, (const int4*)ecol,
                                            (const float4*)eval);

    cudaEventRecord(eJoin, s2);
    cudaStreamWaitEvent(0, eJoin, 0);

    spmm4<<<N_NODES / 8, 256>>>(out, bias);                    // join, then SpMM
}

// round 13
// speedup vs baseline: 1.6192x; 1.6192x over previous
#include <cuda_runtime.h>
#include <cuda_fp16.h>
#include <cstdint>

#define N_NODES 65536
#define N_EDGES 1048576
#define FEAT    64

// ------------------------- device scratch (no allocs) -----------------------
__device__ __align__(16) __half g_support_h[(size_t)N_NODES * FEAT]; // 8 MB
__device__ __align__(16) int   g_cnt[N_NODES];   // zero-init; self-cleaned per run
__device__ __align__(16) int   g_rs[N_NODES + 4];
__device__ __align__(16) int   g_cur[N_NODES];
__device__ __align__(16) int   g_bsum[64];
__device__ __align__(16) int2  g_epair[N_EDGES];
__device__ unsigned g_barcnt;
__device__ unsigned g_bargen;

// ---- packed f32x2 helpers ---------------------------------------------------
__device__ __forceinline__ unsigned long long pk2(float x, float y) {
    unsigned long long r;
    asm("mov.b64 %0, {%1, %2};" : "=l"(r) : "f"(x), "f"(y));
    return r;
}
__device__ __forceinline__ void fma2(unsigned long long& d,
                                     unsigned long long a, unsigned long long b) {
    asm("fma.rn.f32x2 %0, %1, %2, %0;" : "+l"(d) : "l"(a), "l"(b));
}
__device__ __forceinline__ float2 up2(unsigned long long v) {
    float2 f;
    asm("mov.b64 {%0, %1}, %2;" : "=f"(f.x), "=f"(f.y) : "l"(v));
    return f;
}

// ---------------------------------------------------------------------------
// Kernel 1: GEMM tile (64 rows) + edge-row histogram chunk (1024 edges).
// Hist atomics drain in the shadow of the FMA chains.
// ---------------------------------------------------------------------------
__global__ __launch_bounds__(256) void gemm_hist(const float* __restrict__ X,
                                                 const float* __restrict__ W,
                                                 const int4*  __restrict__ erow4) {
    __shared__ float4 Ws[64][16];
    __shared__ float4 Xs[64][16];

    const int tid  = threadIdx.x;
    const int base = blockIdx.x * 64;

    const float4* X4 = (const float4*)(X + (size_t)base * FEAT);
    const float4* W4 = (const float4*)W;
    float4* XsF = (float4*)Xs;
    float4* WsF = (float4*)Ws;
#pragma unroll
    for (int i = 0; i < 4; i++) {
        const int idx = tid + i * 256;
        XsF[idx] = X4[idx];
        WsF[idx] = W4[idx];
    }

    const int4 r = erow4[blockIdx.x * 256 + tid];
    atomicAdd(&g_cnt[r.x], 1);
    atomicAdd(&g_cnt[r.y], 1);
    atomicAdd(&g_cnt[r.z], 1);
    atomicAdd(&g_cnt[r.w], 1);

    __syncthreads();

    const int rt = tid >> 4;
    const int ct = tid & 15;

    unsigned long long acc[4][2];
#pragma unroll
    for (int i = 0; i < 4; i++) { acc[i][0] = pk2(0.f, 0.f); acc[i][1] = pk2(0.f, 0.f); }

#pragma unroll
    for (int kk = 0; kk < 16; kk++) {
        const float4 w0 = Ws[kk * 4 + 0][ct];
        const float4 w1 = Ws[kk * 4 + 1][ct];
        const float4 w2 = Ws[kk * 4 + 2][ct];
        const float4 w3 = Ws[kk * 4 + 3][ct];
        const unsigned long long wp00 = pk2(w0.x, w0.y), wp01 = pk2(w0.z, w0.w);
        const unsigned long long wp10 = pk2(w1.x, w1.y), wp11 = pk2(w1.z, w1.w);
        const unsigned long long wp20 = pk2(w2.x, w2.y), wp21 = pk2(w2.z, w2.w);
        const unsigned long long wp30 = pk2(w3.x, w3.y), wp31 = pk2(w3.z, w3.w);
#pragma unroll
        for (int i = 0; i < 4; i++) {
            const float4 x = Xs[rt + 16 * i][kk];
            unsigned long long xx;
            xx = pk2(x.x, x.x); fma2(acc[i][0], xx, wp00); fma2(acc[i][1], xx, wp01);
            xx = pk2(x.y, x.y); fma2(acc[i][0], xx, wp10); fma2(acc[i][1], xx, wp11);
            xx = pk2(x.z, x.z); fma2(acc[i][0], xx, wp20); fma2(acc[i][1], xx, wp21);
            xx = pk2(x.w, x.w); fma2(acc[i][0], xx, wp30); fma2(acc[i][1], xx, wp31);
        }
    }

#pragma unroll
    for (int i = 0; i < 4; i++) {
        const int row = base + rt + 16 * i;
        const float2 a = up2(acc[i][0]);
        const float2 b = up2(acc[i][1]);
        const __half2 ha = __floats2half2_rn(a.x, a.y);
        const __half2 hb = __floats2half2_rn(b.x, b.y);
        uint2 st;
        st.x = *(const unsigned*)&ha;
        st.y = *(const unsigned*)&hb;
        *(uint2*)(g_support_h + (size_t)row * FEAT + ct * 4) = st;
    }
}

// ---------------------------------------------------------------------------
// Kernel 2: full CSR scan (64 blocks, internal grid barrier). Self-cleans cnt.
// ---------------------------------------------------------------------------
__device__ __forceinline__ void gbar64() {
    __syncthreads();
    if (threadIdx.x == 0) {
        __threadfence();
        const unsigned gen = *(volatile unsigned*)&g_bargen;
        if (atomicAdd(&g_barcnt, 1u) == 63u) {
            g_barcnt = 0;
            __threadfence();
            *(volatile unsigned*)&g_bargen = gen + 1u;
        } else {
            while (*(volatile unsigned*)&g_bargen == gen) { __nanosleep(32); }
        }
    }
    __syncthreads();
}

__global__ __launch_bounds__(256) void scan_fused() {
    __shared__ int wsum[8];
    const int tid = threadIdx.x;
    const int bid = blockIdx.x;
    const int i = bid * 256 + tid;

    const int4 c = ((const int4*)g_cnt)[i];
    const int s = c.x + c.y + c.z + c.w;

    const int lane = tid & 31, wid = tid >> 5;
    int x = s;
#pragma unroll
    for (int d = 1; d < 32; d <<= 1) {
        const int y = __shfl_up_sync(0xFFFFFFFFu, x, d);
        if (lane >= d) x += y;
    }
    if (lane == 31) wsum[wid] = x;
    __syncthreads();
    if (wid == 0) {
        int w = (lane < 8) ? wsum[lane] : 0;
#pragma unroll
        for (int d = 1; d < 8; d <<= 1) {
            const int y = __shfl_up_sync(0xFFFFFFFFu, w, d);
            if (lane >= d) w += y;
        }
        if (lane < 8) wsum[lane] = w;
    }
    __syncthreads();
    const int incl = x + (wid > 0 ? wsum[wid - 1] : 0);
    const int ex = incl - s;
    if (tid == 255) g_bsum[bid] = incl;
    gbar64();

    if (bid == 0 && tid < 32) {
        const int a = __ldcg(&g_bsum[tid]);
        const int b = __ldcg(&g_bsum[tid + 32]);
        int ia = a, ib = b;
#pragma unroll
        for (int d = 1; d < 32; d <<= 1) {
            const int ya = __shfl_up_sync(0xFFFFFFFFu, ia, d);
            const int yb = __shfl_up_sync(0xFFFFFFFFu, ib, d);
            if (tid >= d) { ia += ya; ib += yb; }
        }
        const int lowtot = __shfl_sync(0xFFFFFFFFu, ia, 31);
        g_bsum[tid]      = ia - a;
        g_bsum[tid + 32] = lowtot + ib - b;
    }
    gbar64();

    const int off = __ldcg(&g_bsum[bid]) + ex;
    const int4 rs = make_int4(off, off + c.x, off + c.x + c.y, off + c.x + c.y + c.z);
    ((int4*)g_rs)[i]  = rs;
    ((int4*)g_cur)[i] = rs;
    ((int4*)g_cnt)[i] = make_int4(0, 0, 0, 0);
    if (i == 0) g_rs[N_NODES] = N_EDGES;
}

// ---------------------------------------------------------------------------
// Kernel 3: reorder edges into CSR (col, val) pairs
// ---------------------------------------------------------------------------
__global__ __launch_bounds__(256) void reorder(const int4*   __restrict__ erow4,
                                               const int4*   __restrict__ ecol4,
                                               const float4* __restrict__ eval4) {
    const unsigned i = blockIdx.x * 256u + threadIdx.x;
    const int4   r = erow4[i];
    const int4   c = ecol4[i];
    const float4 v = eval4[i];
    int p;
    p = atomicAdd(&g_cur[r.x], 1); g_epair[p] = make_int2(c.x, __float_as_int(v.x));
    p = atomicAdd(&g_cur[r.y], 1); g_epair[p] = make_int2(c.y, __float_as_int(v.y));
    p = atomicAdd(&g_cur[r.z], 1); g_epair[p] = make_int2(c.z, __float_as_int(v.z));
    p = atomicAdd(&g_cur[r.w], 1); g_epair[p] = make_int2(c.w, __float_as_int(v.w));
}

// ---------------------------------------------------------------------------
// Kernel 4: SpMM + bias + ReLU, 8 threads/row, SOFTWARE-PIPELINED unroll-4.
// All 4 epair loads issue before the 4 gathers -> MLP 4 on both stages.
// ---------------------------------------------------------------------------
__global__ __launch_bounds__(256) void spmm_fused(float* __restrict__ out,
                                                  const float* __restrict__ bias) {
    const int r  = blockIdx.x * 32 + (threadIdx.x >> 3);
    const int qi = threadIdx.x & 7;

    const int s = g_rs[r];
    const int e = g_rs[r + 1];
    const __half* supp = g_support_h;

    float acc[8];
#pragma unroll
    for (int j = 0; j < 8; j++) acc[j] = 0.f;

    int i = s;
    // main loop: 4 edges per iteration, loads batched for MLP=4
    for (; i + 4 <= e; i += 4) {
        const int2 p0 = g_epair[i + 0];
        const int2 p1 = g_epair[i + 1];
        const int2 p2 = g_epair[i + 2];
        const int2 p3 = g_epair[i + 3];
        const uint4 h0 = *(const uint4*)(supp + ((size_t)p0.x << 6) + (qi << 3));
        const uint4 h1 = *(const uint4*)(supp + ((size_t)p1.x << 6) + (qi << 3));
        const uint4 h2 = *(const uint4*)(supp + ((size_t)p2.x << 6) + (qi << 3));
        const uint4 h3 = *(const uint4*)(supp + ((size_t)p3.x << 6) + (qi << 3));
        const float v0 = __int_as_float(p0.y);
        const float v1 = __int_as_float(p1.y);
        const float v2 = __int_as_float(p2.y);
        const float v3 = __int_as_float(p3.y);
        float2 f;
        f = __half22float2(*(const __half2*)&h0.x); acc[0] += v0 * f.x; acc[1] += v0 * f.y;
        f = __half22float2(*(const __half2*)&h0.y); acc[2] += v0 * f.x; acc[3] += v0 * f.y;
        f = __half22float2(*(const __half2*)&h0.z); acc[4] += v0 * f.x; acc[5] += v0 * f.y;
        f = __half22float2(*(const __half2*)&h0.w); acc[6] += v0 * f.x; acc[7] += v0 * f.y;
        f = __half22float2(*(const __half2*)&h1.x); acc[0] += v1 * f.x; acc[1] += v1 * f.y;
        f = __half22float2(*(const __half2*)&h1.y); acc[2] += v1 * f.x; acc[3] += v1 * f.y;
        f = __half22float2(*(const __half2*)&h1.z); acc[4] += v1 * f.x; acc[5] += v1 * f.y;
        f = __half22float2(*(const __half2*)&h1.w); acc[6] += v1 * f.x; acc[7] += v1 * f.y;
        f = __half22float2(*(const __half2*)&h2.x); acc[0] += v2 * f.x; acc[1] += v2 * f.y;
        f = __half22float2(*(const __half2*)&h2.y); acc[2] += v2 * f.x; acc[3] += v2 * f.y;
        f = __half22float2(*(const __half2*)&h2.z); acc[4] += v2 * f.x; acc[5] += v2 * f.y;
        f = __half22float2(*(const __half2*)&h2.w); acc[6] += v2 * f.x; acc[7] += v2 * f.y;
        f = __half22float2(*(const __half2*)&h3.x); acc[0] += v3 * f.x; acc[1] += v3 * f.y;
        f = __half22float2(*(const __half2*)&h3.y); acc[2] += v3 * f.x; acc[3] += v3 * f.y;
        f = __half22float2(*(const __half2*)&h3.z); acc[4] += v3 * f.x; acc[5] += v3 * f.y;
        f = __half22float2(*(const __half2*)&h3.w); acc[6] += v3 * f.x; acc[7] += v3 * f.y;
    }
    // tail
    for (; i < e; i++) {
        const int2 p0 = g_epair[i];
        const float v0 = __int_as_float(p0.y);
        const uint4 h0 = *(const uint4*)(supp + ((size_t)p0.x << 6) + (qi << 3));
        float2 f;
        f = __half22float2(*(const __half2*)&h0.x); acc[0] += v0 * f.x; acc[1] += v0 * f.y;
        f = __half22float2(*(const __half2*)&h0.y); acc[2] += v0 * f.x; acc[3] += v0 * f.y;
        f = __half22float2(*(const __half2*)&h0.z); acc[4] += v0 * f.x; acc[5] += v0 * f.y;
        f = __half22float2(*(const __half2*)&h0.w); acc[6] += v0 * f.x; acc[7] += v0 * f.y;
    }

    const float4 b0 = *(const float4*)(bias + qi * 8);
    const float4 b1 = *(const float4*)(bias + qi * 8 + 4);
    float4 o0, o1;
    o0.x = fmaxf(acc[0] + b0.x, 0.f); o0.y = fmaxf(acc[1] + b0.y, 0.f);
    o0.z = fmaxf(acc[2] + b0.z, 0.f); o0.w = fmaxf(acc[3] + b0.w, 0.f);
    o1.x = fmaxf(acc[4] + b1.x, 0.f); o1.y = fmaxf(acc[5] + b1.y, 0.f);
    o1.z = fmaxf(acc[6] + b1.z, 0.f); o1.w = fmaxf(acc[7] + b1.w, 0.f);
    float* po = out + (size_t)r * FEAT + qi * 8;
    *(float4*)po       = o0;
    *(float4*)(po + 4) = o1;
}

// ---------------------------------------------------------------------------
extern "C" void kernel_launch(void* const* d_in, const int* in_sizes, int n_in,
                              void* d_out, int out_size) {
    const float* X    = (const float*)d_in[0];
    const int*   erow = (const int*)  d_in[1];
    const int*   ecol = (const int*)  d_in[2];
    const float* eval = (const float*)d_in[3];
    const float* W    = (const float*)d_in[4];
    const float* bias = (const float*)d_in[5];
    float* out = (float*)d_out;

    gemm_hist<<<N_NODES / 64, 256>>>(X, W, (const int4*)erow);
    scan_fused<<<64, 256>>>();
    reorder<<<N_EDGES / 1024, 256>>>((const int4*)erow, (const int4*)ecol,
                                     (const float4*)eval);
    spmm_fused<<<N_NODES / 32, 256>>>(out, bias);
}